// round 1
// baseline (speedup 1.0000x reference)
#include <cuda_runtime.h>

// DeEmphasis: y[n] = x[n] + ALPHA*y[n-1], zero init, per row (64 x 960000 fp32).
//
// Strategy: exponential forgetting => chunks with a 192-sample halo are
// independent to fp32 precision (0.85^192 ~ 2e-14). 7680 fully parallel
// blocks, each: coalesced load -> padded smem -> per-thread serial scan of
// 32 regs -> warp affine scan (coef alpha^32) -> cross-warp carry via smem
// (alpha^1024 underflows, so no cross-warp scan needed) -> rescan with true
// entering state -> smem -> coalesced store.

#define ALPHA 0.85f

static constexpr int ROWLEN  = 960000;
static constexpr int CHUNK   = 8000;   // payload per block
static constexpr int HALO    = 192;    // alpha^192 ~ 2e-14, below fp32 eps
static constexpr int TOTAL   = CHUNK + HALO;      // 8192
static constexpr int THREADS = 256;
static constexpr int SEG     = TOTAL / THREADS;   // 32 elems per thread
static constexpr int SPAD    = TOTAL + TOTAL / 32; // 8448 floats, +1 pad / 32

// compile-time alpha^n
__host__ __device__ constexpr float apow(int n) {
    double r = 1.0;
    for (int i = 0; i < n; i++) r *= (double)ALPHA;
    return (float)r;
}

__global__ void __launch_bounds__(THREADS, 4)
deemph_kernel(const float* __restrict__ x, float* __restrict__ y)
{
    const int chunk = blockIdx.x;          // 0..119
    const int row   = blockIdx.y;          // 0..63
    const int tid   = threadIdx.x;
    const int lane  = tid & 31;
    const int w     = tid >> 5;

    __shared__ float s[SPAD];
    __shared__ float wsum[THREADS / 32];

    const int rowbase = row * ROWLEN;
    const int cstart  = chunk * CHUNK - HALO;   // first (halo) column, may be <0

    // ---- stage in: coalesced global -> padded smem ----
    #pragma unroll
    for (int p = 0; p < TOTAL / THREADS; p++) {
        int i   = tid + p * THREADS;
        int col = cstart + i;
        float v = (col >= 0) ? x[rowbase + col] : 0.0f;   // zero-init history
        s[i + (i >> 5)] = v;
    }
    __syncthreads();

    // ---- per-thread segment into registers (conflict-free: bank = (tid+j)%32) ----
    float xv[SEG];
    const int sbase = tid * (SEG + 1);   // SEG=32 -> stride 33
    #pragma unroll
    for (int j = 0; j < SEG; j++) xv[j] = s[sbase + j];

    // pass 1: segment total with zero entering state
    float b = 0.0f;
    #pragma unroll
    for (int j = 0; j < SEG; j++) b = fmaf(ALPHA, b, xv[j]);

    // ---- warp Kogge-Stone affine scan, per-segment coefficient A = alpha^32 ----
    const float A32 = apow(SEG);         // ~5.513e-3
    float cp = A32;
    float v  = b;
    #pragma unroll
    for (int d = 1; d < 32; d <<= 1) {
        float up = __shfl_up_sync(0xffffffffu, v, d);
        if (lane >= d) v = fmaf(cp, up, v);
        cp *= cp;
    }
    if (lane == 31) wsum[w] = v;   // warp-local end state (entering state 0)
    __syncthreads();

    // cross-warp carry: alpha^(32*32) underflows to 0, so the true state at a
    // warp boundary is exactly the previous warp's local total. No scan needed.
    float carry = (w > 0) ? wsum[w - 1] : 0.0f;

    // pass 2 scan with carry injected at lane 0 (adds A32^(t+1)*carry to incl_t)
    float b2 = b + ((lane == 0) ? A32 * carry : 0.0f);
    cp = A32;
    v  = b2;
    #pragma unroll
    for (int d = 1; d < 32; d <<= 1) {
        float up = __shfl_up_sync(0xffffffffu, v, d);
        if (lane >= d) v = fmaf(cp, up, v);
        cp *= cp;
    }
    float excl = __shfl_up_sync(0xffffffffu, v, 1);  // entering state for my segment
    if (lane == 0) excl = carry;

    // ---- final pass: rescan segment with true entering state, write to smem ----
    float yv = excl;
    #pragma unroll
    for (int j = 0; j < SEG; j++) {
        yv = fmaf(ALPHA, yv, xv[j]);
        s[sbase + j] = yv;
    }
    __syncthreads();

    // ---- stage out: padded smem -> coalesced global (skip halo) ----
    const int obase = rowbase + chunk * CHUNK;
    #pragma unroll
    for (int p = 0; p < (CHUNK + THREADS - 1) / THREADS; p++) {
        int i = tid + p * THREADS;
        if (i < CHUNK) {
            int si = i + HALO;
            y[obase + i] = s[si + (si >> 5)];
        }
    }
}

extern "C" void kernel_launch(void* const* d_in, const int* in_sizes, int n_in,
                              void* d_out, int out_size)
{
    const float* x = (const float*)d_in[0];
    float*       y = (float*)d_out;

    const int n    = in_sizes[0];          // 61,440,000
    const int rows = n / ROWLEN;           // 64
    dim3 grid(ROWLEN / CHUNK, rows);       // (120, 64)
    deemph_kernel<<<grid, THREADS>>>(x, y);
}